// round 1
// baseline (speedup 1.0000x reference)
#include <cuda_runtime.h>
#include <math.h>

// Problem dims (fixed by reference)
#define BB   256          // batch
#define TT   8            // context size
#define HH   1024         // hidden
#define VV   32000        // vocab
#define G4   4096         // 4*H (gates flattened)

// ---------------------------------------------------------------------------
// Scratch (device globals -> allowed; no cudaMalloc anywhere)
// ---------------------------------------------------------------------------
__device__ float g_h[TT][BB][HH];   // h_t for every timestep (feeds batched logits GEMM)
__device__ float g_c[BB][HH];       // cell state (rolling)
__device__ float g_acc[BB][G4];     // recurrent GEMM output (pre-activation, before x*Wx + bh)

// ---------------------------------------------------------------------------
// Tiled NT SGEMM body: C[m,n] = sum_k A[m,k] * B[n,k]  (+ bias[n])
// A: (M x K) row-major, lda = K.  B: (N x K) row-major, ldb = K.
// Tile: BM=BN=64, BK=16, 256 threads (16x16), 4x4 micro-tile per thread.
// K must be a multiple of 16; M,N multiples of 64 (true here: 256/4096/32000/1024).
// ---------------------------------------------------------------------------
__device__ __forceinline__ void gemm_nt_body(
    const float* __restrict__ A, const float* __restrict__ Bm,
    const float* __restrict__ bias, float* __restrict__ C,
    int K, int ldc, int m0, int n0)
{
    __shared__ float As[16][64];
    __shared__ float Bs[16][64];

    const int tid = threadIdx.x;        // 0..255
    const int tx  = tid & 15;           // 0..15  (n direction)
    const int ty  = tid >> 4;           // 0..15  (m direction)

    // loader mapping: 256 threads cover 64 rows x 16 k (one float4 each)
    const int lrow = tid >> 2;          // 0..63
    const int lk4  = (tid & 3) * 4;     // 0,4,8,12

    const float* Aptr = A  + (size_t)(m0 + lrow) * K + lk4;
    const float* Bptr = Bm + (size_t)(n0 + lrow) * K + lk4;

    float acc[4][4] = {};

    for (int k0 = 0; k0 < K; k0 += 16) {
        float4 a4 = *(const float4*)(Aptr + k0);
        float4 b4 = *(const float4*)(Bptr + k0);
        As[lk4 + 0][lrow] = a4.x;
        As[lk4 + 1][lrow] = a4.y;
        As[lk4 + 2][lrow] = a4.z;
        As[lk4 + 3][lrow] = a4.w;
        Bs[lk4 + 0][lrow] = b4.x;
        Bs[lk4 + 1][lrow] = b4.y;
        Bs[lk4 + 2][lrow] = b4.z;
        Bs[lk4 + 3][lrow] = b4.w;
        __syncthreads();

        #pragma unroll
        for (int k = 0; k < 16; k++) {
            float4 av = *(const float4*)&As[k][ty * 4];
            float4 bv = *(const float4*)&Bs[k][tx * 4];
            float am[4] = {av.x, av.y, av.z, av.w};
            float bn[4] = {bv.x, bv.y, bv.z, bv.w};
            #pragma unroll
            for (int i = 0; i < 4; i++)
                #pragma unroll
                for (int j = 0; j < 4; j++)
                    acc[i][j] = fmaf(am[i], bn[j], acc[i][j]);
        }
        __syncthreads();
    }

    #pragma unroll
    for (int i = 0; i < 4; i++) {
        const int m = m0 + ty * 4 + i;
        #pragma unroll
        for (int j = 0; j < 4; j++) {
            const int n = n0 + tx * 4 + j;
            float v = acc[i][j];
            if (bias) v += bias[n];
            C[(size_t)m * ldc + n] = v;
        }
    }
}

// Recurrent GEMM for step t: g_acc = g_h[t-1] @ Wh[t]^T  (Wh[t] viewed as 4096 x 1024)
__global__ void gemm_pre_kernel(const float* __restrict__ Wh, int t)
{
    const float* A  = &g_h[t - 1][0][0];
    const float* Bm = Wh + (size_t)t * G4 * HH;
    gemm_nt_body(A, Bm, nullptr, &g_acc[0][0], HH, G4,
                 blockIdx.y * 64, blockIdx.x * 64);
}

// Batched logits GEMM: out[b, t, v] = g_h[t][b,:] . Wout[t][v,:] + bout[t][v]
__global__ void gemm_logits_kernel(const float* __restrict__ Wout,
                                   const float* __restrict__ bout,
                                   float* __restrict__ out)
{
    const int t = blockIdx.z;
    const float* A    = &g_h[t][0][0];
    const float* Bm   = Wout + (size_t)t * VV * HH;
    const float* bias = bout + (size_t)t * VV;
    // out row stride over batch is TT*VV; timestep offset t*VV
    gemm_nt_body(A, Bm, bias, out + (size_t)t * VV, HH, TT * VV,
                 blockIdx.y * 64, blockIdx.x * 64);
}

// ---------------------------------------------------------------------------
// Gates / cell update. first=1 means t==0: pre = x*Wx only (no Wh, no bh term).
// ---------------------------------------------------------------------------
__device__ __forceinline__ float sigf(float v) { return 1.0f / (1.0f + expf(-v)); }

__global__ void gates_kernel(const float* __restrict__ x,
                             const float* __restrict__ Wx,
                             const float* __restrict__ bh,
                             int t, int first)
{
    const int idx = blockIdx.x * blockDim.x + threadIdx.x;  // 0 .. BB*HH-1
    const int b  = idx >> 10;
    const int hh = idx & (HH - 1);

    const float xb = x[b * TT + t];
    const float* wx  = Wx + (size_t)t * 4 * HH;   // Wx[t] : (4, H, 1)
    const float* bht = bh + (size_t)t * 4 * HH;   // bh[t] : (4, H)
    const float* acc = &g_acc[b][0];

    float p[4];
    #pragma unroll
    for (int g = 0; g < 4; g++) {
        float v = xb * wx[g * HH + hh];
        if (!first) v += acc[g * HH + hh] + bht[g * HH + hh];
        p[g] = v;
    }

    const float f_  = sigf(p[0]);
    const float i_  = sigf(p[1]);
    const float cb  = tanhf(p[2]);
    const float o_  = sigf(p[3]);

    float c = first ? (i_ * cb) : fmaf(f_, g_c[b][hh], i_ * cb);
    g_c[b][hh]     = c;
    g_h[t][b][hh]  = o_ * tanhf(c);
}

// ---------------------------------------------------------------------------
// Entry point
// ---------------------------------------------------------------------------
extern "C" void kernel_launch(void* const* d_in, const int* in_sizes, int n_in,
                              void* d_out, int out_size)
{
    const float* x    = (const float*)d_in[0];  // (B, T)
    const float* Wx   = (const float*)d_in[1];  // (T, 4, H, 1)
    const float* Wh   = (const float*)d_in[2];  // (T, 4, H, H)
    const float* bh   = (const float*)d_in[3];  // (T, 4, H)
    const float* Wout = (const float*)d_in[4];  // (T, V, H)
    const float* bout = (const float*)d_in[5];  // (T, V)
    float* out = (float*)d_out;                 // (B, T, V)

    const int gate_blocks = (BB * HH) / 256;    // 1024

    // t = 0: pre = x*Wx only
    gates_kernel<<<gate_blocks, 256>>>(x, Wx, bh, 0, 1);

    // t = 1..7: recurrent GEMM then gates
    for (int t = 1; t < TT; t++) {
        dim3 gp(G4 / 64, BB / 64);              // (64, 4)
        gemm_pre_kernel<<<gp, 256>>>(Wh, t);
        gates_kernel<<<gate_blocks, 256>>>(x, Wx, bh, t, 0);
    }

    // Batched output projection over all 8 timesteps
    dim3 gl(VV / 64, BB / 64, TT);              // (500, 4, 8)
    gemm_logits_kernel<<<gl, 256>>>(Wout, bout, out);
}

// round 3
// speedup vs baseline: 1.9829x; 1.9829x over previous
#include <cuda_runtime.h>
#include <cuda_bf16.h>
#include <math.h>
#include <stdint.h>

#define BB 256
#define TT 8
#define HH 1024
#define VV 32000
#define G4 4096

#define BM 128
#define BN 128
#define BK 64            // 64 bf16 = 128 B per row (SW128-friendly)
#define NCHUNK (HH / BK) // 16
#define THREADS 256

#define TILE_B  16384            // one 128x64 bf16 tile
#define STAGE_B (4 * TILE_B)     // Ah, Al, Bh, Bl
#define OFF_AH 0
#define OFF_AL 16384
#define OFF_BH 32768
#define OFF_BL 49152
#define SMEM_TOTAL (2 * STAGE_B) // 131072

#define SWZ(off) ((off) ^ (((off) >> 3) & 0x70))

// ---------------------------------------------------------------------------
// scratch (device globals only — no allocation)
// ---------------------------------------------------------------------------
__device__ __nv_bfloat16 g_hh[TT][BB][HH];   // hi split of h
__device__ __nv_bfloat16 g_hl[TT][BB][HH];   // lo split of h
__device__ float g_c[BB][HH];
__device__ float g_acc[BB][G4];

// ---------------------------------------------------------------------------
// PTX helpers (baseline sm_80+ features only: ldmatrix + mma.sync)
// ---------------------------------------------------------------------------
__device__ __forceinline__ uint32_t smem_to_u32(const void* p) {
    uint32_t a;
    asm("{ .reg .u64 t; cvta.to.shared.u64 t, %1; cvt.u32.u64 %0, t; }" : "=r"(a) : "l"(p));
    return a;
}

__device__ __forceinline__ void ldsm4(uint32_t* r, uint32_t addr) {
    asm volatile("ldmatrix.sync.aligned.m8n8.x4.shared.b16 {%0,%1,%2,%3}, [%4];"
                 : "=r"(r[0]), "=r"(r[1]), "=r"(r[2]), "=r"(r[3]) : "r"(addr));
}

__device__ __forceinline__ void mma16816(float* c, const uint32_t* a, const uint32_t* b) {
    asm volatile(
        "mma.sync.aligned.m16n8k16.row.col.f32.bf16.bf16.f32 "
        "{%0,%1,%2,%3}, {%4,%5,%6,%7}, {%8,%9}, {%0,%1,%2,%3};"
        : "+f"(c[0]), "+f"(c[1]), "+f"(c[2]), "+f"(c[3])
        : "r"(a[0]), "r"(a[1]), "r"(a[2]), "r"(a[3]), "r"(b[0]), "r"(b[1]));
}

// pack two fp32 into bf16x2 hi word + bf16x2 lo (residual) word
__device__ __forceinline__ uint32_t split2(float x, float y, uint32_t& lo) {
    __nv_bfloat16 hx = __float2bfloat16(x);
    __nv_bfloat16 hy = __float2bfloat16(y);
    __nv_bfloat16 lx = __float2bfloat16(x - __bfloat162float(hx));
    __nv_bfloat16 ly = __float2bfloat16(y - __bfloat162float(hy));
    __nv_bfloat162 ph; ph.x = hx; ph.y = hy;
    __nv_bfloat162 pl; pl.x = lx; pl.y = ly;
    lo = *(uint32_t*)&pl;
    return *(uint32_t*)&ph;
}

// ---------------------------------------------------------------------------
// Chunk loader: A (pre-split bf16 hi/lo) and B (fp32, split on the fly).
// 256 threads; thread t handles row = t>>1 (0..127), half = t&1 (32 elems).
// ---------------------------------------------------------------------------
__device__ __forceinline__ void load_chunk(const __nv_bfloat16* __restrict__ Ahg,
                                           const __nv_bfloat16* __restrict__ Alg,
                                           const float* __restrict__ Bg,
                                           char* buf, int kc, int tid) {
    const int row  = tid >> 1;
    const int half = tid & 1;
    const uint32_t cbase = (uint32_t)(row * 128 + half * 64);

    // ---- A: raw bf16 copies (hi and lo) ----
    const __nv_bfloat16* ah = Ahg + (size_t)row * HH + kc * BK + half * 32;
    const __nv_bfloat16* al = Alg + (size_t)row * HH + kc * BK + half * 32;
    #pragma unroll
    for (int j = 0; j < 4; j++) {
        uint4 vh = *(const uint4*)(ah + j * 8);
        uint4 vl = *(const uint4*)(al + j * 8);
        const uint32_t off = SWZ(cbase + j * 16);
        *(uint4*)(buf + OFF_AH + off) = vh;
        *(uint4*)(buf + OFF_AL + off) = vl;
    }

    // ---- B: fp32 -> split bf16 ----
    const float* bs = Bg + (size_t)row * HH + kc * BK + half * 32;
    #pragma unroll
    for (int j = 0; j < 4; j++) {
        float4 f0 = *(const float4*)(bs + j * 8);
        float4 f1 = *(const float4*)(bs + j * 8 + 4);
        uint4 vh, vl;
        vh.x = split2(f0.x, f0.y, vl.x);
        vh.y = split2(f0.z, f0.w, vl.y);
        vh.z = split2(f1.x, f1.y, vl.z);
        vh.w = split2(f1.z, f1.w, vl.w);
        const uint32_t off = SWZ(cbase + j * 16);
        *(uint4*)(buf + OFF_BH + off) = vh;
        *(uint4*)(buf + OFF_BL + off) = vl;
    }
}

// ---------------------------------------------------------------------------
// GEMM tile body: C(128x128) = A(128x1024) @ B(128x1024)^T [+ bias]
// Warp layout: 8 warps, wm = wid&3 (m32 each), wn = wid>>2 (n64 each).
// ---------------------------------------------------------------------------
__device__ __forceinline__ void gemm_body(const __nv_bfloat16* Ahg,
                                          const __nv_bfloat16* Alg,
                                          const float* Bg, const float* bias,
                                          float* C, int ldc) {
    extern __shared__ char smem[];
    const uint32_t sbase = smem_to_u32(smem);
    const int tid  = threadIdx.x;
    const int lane = tid & 31;
    const int wid  = tid >> 5;
    const int wm   = wid & 3;   // 0..3 -> m32 block
    const int wn   = wid >> 2;  // 0..1 -> n64 block

    float acc[2][8][4];
    #pragma unroll
    for (int mt = 0; mt < 2; mt++)
        #pragma unroll
        for (int nt = 0; nt < 8; nt++)
            #pragma unroll
            for (int i = 0; i < 4; i++) acc[mt][nt][i] = 0.0f;

    // ldmatrix lane-address components (constant across chunks)
    const int a_row = (lane & 15);
    const int a_kb  = (lane >> 4) * 16;
    const int b_row = (lane & 7) + ((lane >> 4) << 3);
    const int b_kb  = ((lane >> 3) & 1) * 16;

    load_chunk(Ahg, Alg, Bg, smem, 0, tid);
    __syncthreads();

    for (int kc = 0; kc < NCHUNK; kc++) {
        const int st = kc & 1;
        if (kc + 1 < NCHUNK)
            load_chunk(Ahg, Alg, Bg, smem + (st ^ 1) * STAGE_B, kc + 1, tid);

        const uint32_t sb = sbase + st * STAGE_B;
        #pragma unroll
        for (int k16 = 0; k16 < 4; k16++) {
            const int kb = k16 * 32;   // byte offset of this k16 within the 128B row

            uint32_t ah[2][4], al[2][4];
            #pragma unroll
            for (int mt = 0; mt < 2; mt++) {
                const uint32_t off = SWZ((uint32_t)((wm * 32 + mt * 16 + a_row) * 128 + kb + a_kb));
                ldsm4(ah[mt], sb + OFF_AH + off);
                ldsm4(al[mt], sb + OFF_AL + off);
            }
            uint32_t bh[8][2], bl[8][2];
            #pragma unroll
            for (int nq = 0; nq < 4; nq++) {
                const uint32_t off = SWZ((uint32_t)((wn * 64 + nq * 16 + b_row) * 128 + kb + b_kb));
                uint32_t r[4];
                ldsm4(r, sb + OFF_BH + off);
                bh[nq * 2][0] = r[0]; bh[nq * 2][1] = r[1];
                bh[nq * 2 + 1][0] = r[2]; bh[nq * 2 + 1][1] = r[3];
                ldsm4(r, sb + OFF_BL + off);
                bl[nq * 2][0] = r[0]; bl[nq * 2][1] = r[1];
                bl[nq * 2 + 1][0] = r[2]; bl[nq * 2 + 1][1] = r[3];
            }
            #pragma unroll
            for (int mt = 0; mt < 2; mt++)
                #pragma unroll
                for (int nt = 0; nt < 8; nt++) {
                    mma16816(acc[mt][nt], ah[mt], bh[nt]);   // Ah*Bh
                    mma16816(acc[mt][nt], ah[mt], bl[nt]);   // Ah*Bl
                    mma16816(acc[mt][nt], al[mt], bh[nt]);   // Al*Bh
                }
        }
        __syncthreads();
    }

    // Epilogue: c0,c1 at (row, col..col+1); c2,c3 at (row+8, ...)
    const int erow = (lane >> 2);
    const int ecol = (lane & 3) * 2;
    #pragma unroll
    for (int mt = 0; mt < 2; mt++) {
        #pragma unroll
        for (int nt = 0; nt < 8; nt++) {
            const int r0 = wm * 32 + mt * 16 + erow;
            const int cc = wn * 64 + nt * 8 + ecol;
            float b0 = 0.f, b1 = 0.f;
            if (bias) { b0 = bias[cc]; b1 = bias[cc + 1]; }
            float2 v0 = make_float2(acc[mt][nt][0] + b0, acc[mt][nt][1] + b1);
            float2 v1 = make_float2(acc[mt][nt][2] + b0, acc[mt][nt][3] + b1);
            *(float2*)(C + (size_t)r0 * ldc + cc)       = v0;
            *(float2*)(C + (size_t)(r0 + 8) * ldc + cc) = v1;
        }
    }
}

// ---------------------------------------------------------------------------
// Global wrappers
// ---------------------------------------------------------------------------
__global__ void __launch_bounds__(THREADS, 1) gemm_rec_tc(const float* __restrict__ Wh, int t) {
    const int mtile = blockIdx.x & 1;
    const int ntile = blockIdx.x >> 1;
    gemm_body(&g_hh[t - 1][mtile * 128][0], &g_hl[t - 1][mtile * 128][0],
              Wh + (size_t)t * G4 * HH + (size_t)ntile * 128 * HH,
              nullptr,
              &g_acc[mtile * 128][ntile * 128], G4);
}

__global__ void __launch_bounds__(THREADS, 1) gemm_log_tc(const float* __restrict__ Wout,
                                                          const float* __restrict__ bout,
                                                          float* __restrict__ out) {
    const int t = blockIdx.z;
    const int mtile = blockIdx.x & 1;   // adjacent blocks share Wout tile (L2 reuse)
    const int ntile = blockIdx.x >> 1;
    gemm_body(&g_hh[t][mtile * 128][0], &g_hl[t][mtile * 128][0],
              Wout + (size_t)t * VV * HH + (size_t)ntile * 128 * HH,
              bout + (size_t)t * VV + ntile * 128,
              out + (size_t)mtile * 128 * TT * VV + (size_t)t * VV + ntile * 128,
              TT * VV);
}

// ---------------------------------------------------------------------------
// Gates / cell update (emits split-bf16 h for the tensor GEMMs)
// ---------------------------------------------------------------------------
__device__ __forceinline__ float sigf(float v) { return 1.0f / (1.0f + expf(-v)); }

__global__ void gates_kernel(const float* __restrict__ x,
                             const float* __restrict__ Wx,
                             const float* __restrict__ bh,
                             int t, int first) {
    const int idx = blockIdx.x * blockDim.x + threadIdx.x;
    const int b = idx >> 10;
    const int hh = idx & (HH - 1);

    const float xb = x[b * TT + t];
    const float* wx  = Wx + (size_t)t * 4 * HH;
    const float* bht = bh + (size_t)t * 4 * HH;
    const float* acc = &g_acc[b][0];

    float p[4];
    #pragma unroll
    for (int g = 0; g < 4; g++) {
        float v = xb * wx[g * HH + hh];
        if (!first) v += acc[g * HH + hh] + bht[g * HH + hh];
        p[g] = v;
    }
    const float f_ = sigf(p[0]);
    const float i_ = sigf(p[1]);
    const float cb = tanhf(p[2]);
    const float o_ = sigf(p[3]);

    float c = first ? (i_ * cb) : fmaf(f_, g_c[b][hh], i_ * cb);
    g_c[b][hh] = c;
    const float hv = o_ * tanhf(c);
    __nv_bfloat16 hhi = __float2bfloat16(hv);
    g_hh[t][b][hh] = hhi;
    g_hl[t][b][hh] = __float2bfloat16(hv - __bfloat162float(hhi));
}

// ---------------------------------------------------------------------------
// Entry point
// ---------------------------------------------------------------------------
extern "C" void kernel_launch(void* const* d_in, const int* in_sizes, int n_in,
                              void* d_out, int out_size) {
    const float* x    = (const float*)d_in[0];
    const float* Wx   = (const float*)d_in[1];
    const float* Wh   = (const float*)d_in[2];
    const float* bh   = (const float*)d_in[3];
    const float* Wout = (const float*)d_in[4];
    const float* bout = (const float*)d_in[5];
    float* out = (float*)d_out;

    cudaFuncSetAttribute(gemm_rec_tc, cudaFuncAttributeMaxDynamicSharedMemorySize, SMEM_TOTAL);
    cudaFuncSetAttribute(gemm_log_tc, cudaFuncAttributeMaxDynamicSharedMemorySize, SMEM_TOTAL);

    const int gate_blocks = (BB * HH) / 256;

    gates_kernel<<<gate_blocks, 256>>>(x, Wx, bh, 0, 1);
    for (int t = 1; t < TT; t++) {
        gemm_rec_tc<<<64, THREADS, SMEM_TOTAL>>>(Wh, t);        // 32 N-tiles x 2 M-tiles
        gates_kernel<<<gate_blocks, 256>>>(x, Wx, bh, t, 0);
    }
    gemm_log_tc<<<dim3(500, 1, TT), THREADS, SMEM_TOTAL>>>(Wout, bout, out);  // 250 N x 2 M x 8 t
}

// round 4
// speedup vs baseline: 3.0473x; 1.5368x over previous
#include <cuda_runtime.h>
#include <cuda_bf16.h>
#include <math.h>
#include <stdint.h>

#define BB 256
#define TT 8
#define HH 1024
#define VV 32000
#define G4 4096

#define BK 64            // k elems per chunk (64 bf16 = 128 B row)
#define NCHUNK (HH / BK) // 16
#define THREADS 512      // 16 warps

#define SWZ(off) ((off) ^ (((off) >> 3) & 0x70))

// ---------------------------------------------------------------------------
// scratch (device globals only)
// ---------------------------------------------------------------------------
__device__ __nv_bfloat16 g_hh[TT][BB][HH];
__device__ __nv_bfloat16 g_hl[TT][BB][HH];
__device__ float g_c[BB][HH];
__device__ float g_acc[BB][G4];

// ---------------------------------------------------------------------------
// PTX helpers (sm_80-level only)
// ---------------------------------------------------------------------------
__device__ __forceinline__ uint32_t smem_to_u32(const void* p) {
    uint32_t a;
    asm("{ .reg .u64 t; cvta.to.shared.u64 t, %1; cvt.u32.u64 %0, t; }" : "=r"(a) : "l"(p));
    return a;
}
__device__ __forceinline__ void ldsm4(uint32_t* r, uint32_t addr) {
    asm volatile("ldmatrix.sync.aligned.m8n8.x4.shared.b16 {%0,%1,%2,%3}, [%4];"
                 : "=r"(r[0]), "=r"(r[1]), "=r"(r[2]), "=r"(r[3]) : "r"(addr));
}
__device__ __forceinline__ void mma16816(float* c, const uint32_t* a, const uint32_t* b) {
    asm volatile(
        "mma.sync.aligned.m16n8k16.row.col.f32.bf16.bf16.f32 "
        "{%0,%1,%2,%3}, {%4,%5,%6,%7}, {%8,%9}, {%0,%1,%2,%3};"
        : "+f"(c[0]), "+f"(c[1]), "+f"(c[2]), "+f"(c[3])
        : "r"(a[0]), "r"(a[1]), "r"(a[2]), "r"(a[3]), "r"(b[0]), "r"(b[1]));
}
__device__ __forceinline__ void cp16(uint32_t dst, const void* src) {
    asm volatile("cp.async.cg.shared.global [%0], [%1], 16;" :: "r"(dst), "l"(src));
}
#define CP_COMMIT() asm volatile("cp.async.commit_group;" ::: "memory")
#define CP_WAIT0()  asm volatile("cp.async.wait_group 0;" ::: "memory")

__device__ __forceinline__ uint32_t split2(float x, float y, uint32_t& lo) {
    __nv_bfloat16 hx = __float2bfloat16(x);
    __nv_bfloat16 hy = __float2bfloat16(y);
    __nv_bfloat16 lx = __float2bfloat16(x - __bfloat162float(hx));
    __nv_bfloat16 ly = __float2bfloat16(y - __bfloat162float(hy));
    __nv_bfloat162 ph; ph.x = hx; ph.y = hy;
    __nv_bfloat162 pl; pl.x = lx; pl.y = ly;
    lo = *(uint32_t*)&pl;
    return *(uint32_t*)&ph;
}

// ---------------------------------------------------------------------------
// Chunk loader. Threads 0..255: A (bf16 hi/lo, via cp.async). Threads 256..511:
// B (fp32 -> split bf16, register path). BN = 32*NT rows of B.
// Stage layout: [Ah 16K][Al 16K][Bh BN*128][Bl BN*128]
// ---------------------------------------------------------------------------
template <int NT>
__device__ __forceinline__ void load_chunk(const __nv_bfloat16* __restrict__ Ahg,
                                           const __nv_bfloat16* __restrict__ Alg,
                                           const float* __restrict__ Bg,
                                           char* buf, uint32_t bufu, int kc, int tid) {
    constexpr int BN = 32 * NT;
    constexpr int OFF_AH = 0;
    constexpr int OFF_AL = 16384;
    constexpr int OFF_BH = 32768;
    constexpr int OFF_BL = 32768 + BN * 128;

    if (tid < 256) {
        const int row = tid >> 1;
        const int half = tid & 1;
        const uint32_t cbase = (uint32_t)(row * 128 + half * 64);
        const __nv_bfloat16* ah = Ahg + (size_t)row * HH + kc * BK + half * 32;
        const __nv_bfloat16* al = Alg + (size_t)row * HH + kc * BK + half * 32;
        #pragma unroll
        for (int j = 0; j < 4; j++) {
            const uint32_t off = SWZ(cbase + j * 16);
            cp16(bufu + OFF_AH + off, ah + j * 8);
            cp16(bufu + OFF_AL + off, al + j * 8);
        }
    } else {
        const int tid2 = tid - 256;
        constexpr int ITERS = (BN * 64) / (256 * 16);
        #pragma unroll
        for (int it = 0; it < ITERS; it++) {
            const int idx = (tid2 + it * 256) * 16;
            const int row = idx >> 6;
            const int col = idx & 63;            // multiple of 16
            const float* bs = Bg + (size_t)row * HH + kc * BK + col;
            float4 f0 = *(const float4*)(bs + 0);
            float4 f1 = *(const float4*)(bs + 4);
            float4 f2 = *(const float4*)(bs + 8);
            float4 f3 = *(const float4*)(bs + 12);
            uint4 vh0, vl0, vh1, vl1;
            vh0.x = split2(f0.x, f0.y, vl0.x);
            vh0.y = split2(f0.z, f0.w, vl0.y);
            vh0.z = split2(f1.x, f1.y, vl0.z);
            vh0.w = split2(f1.z, f1.w, vl0.w);
            vh1.x = split2(f2.x, f2.y, vl1.x);
            vh1.y = split2(f2.z, f2.w, vl1.y);
            vh1.z = split2(f3.x, f3.y, vl1.z);
            vh1.w = split2(f3.z, f3.w, vl1.w);
            const uint32_t cb = (uint32_t)(row * 128 + col * 2);
            const uint32_t o0 = SWZ(cb);
            const uint32_t o1 = SWZ(cb + 16);
            *(uint4*)(buf + OFF_BH + o0) = vh0;
            *(uint4*)(buf + OFF_BH + o1) = vh1;
            *(uint4*)(buf + OFF_BL + o0) = vl0;
            *(uint4*)(buf + OFF_BL + o1) = vl1;
        }
    }
}

// ---------------------------------------------------------------------------
// GEMM tile: C(128 x 32*NT*4/...) — CTA tile 128 x (128*NT/4). Warp m32 x n(8*NT).
// 16 warps: wm = wid&3, wn = wid>>2 (0..3). BN = 32*NT.
// ---------------------------------------------------------------------------
template <int NT>
__device__ __forceinline__ void gemm_body(const __nv_bfloat16* Ahg,
                                          const __nv_bfloat16* Alg,
                                          const float* Bg, const float* bias,
                                          float* C, int ldc) {
    constexpr int BN = 32 * NT;
    constexpr int OFF_AH = 0;
    constexpr int OFF_AL = 16384;
    constexpr int OFF_BH = 32768;
    constexpr int OFF_BL = 32768 + BN * 128;
    constexpr int STAGE  = 32768 + 2 * BN * 128;

    extern __shared__ char smem[];
    const uint32_t sbase = smem_to_u32(smem);
    const int tid  = threadIdx.x;
    const int lane = tid & 31;
    const int wid  = tid >> 5;
    const int wm   = wid & 3;          // m32 block
    const int wn   = (wid >> 2) & 3;   // n(8*NT) block

    float acc[2][NT][4];
    #pragma unroll
    for (int mt = 0; mt < 2; mt++)
        #pragma unroll
        for (int nt = 0; nt < NT; nt++)
            #pragma unroll
            for (int i = 0; i < 4; i++) acc[mt][nt][i] = 0.0f;

    const int a_row = (lane & 15);
    const int a_kb  = (lane >> 4) * 16;
    const int b_row = (lane & 7) + ((lane >> 4) << 3);
    const int b_kb  = ((lane >> 3) & 1) * 16;

    load_chunk<NT>(Ahg, Alg, Bg, smem, sbase, 0, tid);
    CP_COMMIT();
    CP_WAIT0();
    __syncthreads();

    for (int kc = 0; kc < NCHUNK; kc++) {
        const int st = kc & 1;
        if (kc + 1 < NCHUNK) {
            load_chunk<NT>(Ahg, Alg, Bg, smem + (st ^ 1) * STAGE,
                           sbase + (st ^ 1) * STAGE, kc + 1, tid);
            CP_COMMIT();
        }

        const uint32_t sb = sbase + st * STAGE;
        #pragma unroll
        for (int k16 = 0; k16 < 4; k16++) {
            const int kb = k16 * 32;
            uint32_t ah[2][4], al[2][4];
            #pragma unroll
            for (int mt = 0; mt < 2; mt++) {
                const uint32_t off = SWZ((uint32_t)((wm * 32 + mt * 16 + a_row) * 128 + kb + a_kb));
                ldsm4(ah[mt], sb + OFF_AH + off);
                ldsm4(al[mt], sb + OFF_AL + off);
            }
            uint32_t bh[NT][2], bl[NT][2];
            #pragma unroll
            for (int nq = 0; nq < NT / 2; nq++) {
                const uint32_t off = SWZ((uint32_t)((wn * NT * 8 + nq * 16 + b_row) * 128 + kb + b_kb));
                uint32_t r[4];
                ldsm4(r, sb + OFF_BH + off);
                bh[nq * 2][0] = r[0]; bh[nq * 2][1] = r[1];
                bh[nq * 2 + 1][0] = r[2]; bh[nq * 2 + 1][1] = r[3];
                ldsm4(r, sb + OFF_BL + off);
                bl[nq * 2][0] = r[0]; bl[nq * 2][1] = r[1];
                bl[nq * 2 + 1][0] = r[2]; bl[nq * 2 + 1][1] = r[3];
            }
            #pragma unroll
            for (int mt = 0; mt < 2; mt++)
                #pragma unroll
                for (int nt = 0; nt < NT; nt++) {
                    mma16816(acc[mt][nt], ah[mt], bh[nt]);
                    mma16816(acc[mt][nt], ah[mt], bl[nt]);
                    mma16816(acc[mt][nt], al[mt], bh[nt]);
                }
        }
        if (kc + 1 < NCHUNK) CP_WAIT0();
        __syncthreads();
    }

    const int erow = (lane >> 2);
    const int ecol = (lane & 3) * 2;
    #pragma unroll
    for (int mt = 0; mt < 2; mt++) {
        #pragma unroll
        for (int nt = 0; nt < NT; nt++) {
            const int r0 = wm * 32 + mt * 16 + erow;
            const int cc = wn * NT * 8 + nt * 8 + ecol;
            float b0 = 0.f, b1 = 0.f;
            if (bias) { b0 = bias[cc]; b1 = bias[cc + 1]; }
            float2 v0 = make_float2(acc[mt][nt][0] + b0, acc[mt][nt][1] + b1);
            float2 v1 = make_float2(acc[mt][nt][2] + b0, acc[mt][nt][3] + b1);
            *(float2*)(C + (size_t)r0 * ldc + cc)       = v0;
            *(float2*)(C + (size_t)(r0 + 8) * ldc + cc) = v1;
        }
    }
}

// ---------------------------------------------------------------------------
// Global wrappers
// ---------------------------------------------------------------------------
#define SMEM_REC (2 * (32768 + 2 * 64 * 128))    //  98304 (NT=2, BN=64)
#define SMEM_LOG (2 * (32768 + 2 * 128 * 128))   // 131072 (NT=4, BN=128)

__global__ void __launch_bounds__(THREADS, 1) gemm_rec_tc(const float* __restrict__ Wh, int t) {
    const int mtile = blockIdx.x & 1;
    const int ntile = blockIdx.x >> 1;           // 0..63, BN=64
    gemm_body<2>(&g_hh[t - 1][mtile * 128][0], &g_hl[t - 1][mtile * 128][0],
                 Wh + (size_t)t * G4 * HH + (size_t)ntile * 64 * HH,
                 nullptr,
                 &g_acc[mtile * 128][ntile * 64], G4);
}

__global__ void __launch_bounds__(THREADS, 1) gemm_log_tc(const float* __restrict__ Wout,
                                                          const float* __restrict__ bout,
                                                          float* __restrict__ out) {
    const int t = blockIdx.z;
    const int mtile = blockIdx.x & 1;            // adjacent CTAs share Wout tile via L2
    const int ntile = blockIdx.x >> 1;           // 0..249, BN=128
    gemm_body<4>(&g_hh[t][mtile * 128][0], &g_hl[t][mtile * 128][0],
                 Wout + (size_t)t * VV * HH + (size_t)ntile * 128 * HH,
                 bout + (size_t)t * VV + ntile * 128,
                 out + (size_t)mtile * 128 * TT * VV + (size_t)t * VV + ntile * 128,
                 TT * VV);
}

// ---------------------------------------------------------------------------
// Gates / cell update (emits split-bf16 h)
// ---------------------------------------------------------------------------
__device__ __forceinline__ float sigf(float v) { return 1.0f / (1.0f + expf(-v)); }

__global__ void gates_kernel(const float* __restrict__ x,
                             const float* __restrict__ Wx,
                             const float* __restrict__ bh,
                             int t, int first) {
    const int idx = blockIdx.x * blockDim.x + threadIdx.x;
    const int b = idx >> 10;
    const int hh = idx & (HH - 1);

    const float xb = x[b * TT + t];
    const float* wx  = Wx + (size_t)t * 4 * HH;
    const float* bht = bh + (size_t)t * 4 * HH;
    const float* acc = &g_acc[b][0];

    float p[4];
    #pragma unroll
    for (int g = 0; g < 4; g++) {
        float v = xb * wx[g * HH + hh];
        if (!first) v += acc[g * HH + hh] + bht[g * HH + hh];
        p[g] = v;
    }
    const float f_ = sigf(p[0]);
    const float i_ = sigf(p[1]);
    const float cb = tanhf(p[2]);
    const float o_ = sigf(p[3]);

    float c = first ? (i_ * cb) : fmaf(f_, g_c[b][hh], i_ * cb);
    g_c[b][hh] = c;
    const float hv = o_ * tanhf(c);
    __nv_bfloat16 hhi = __float2bfloat16(hv);
    g_hh[t][b][hh] = hhi;
    g_hl[t][b][hh] = __float2bfloat16(hv - __bfloat162float(hhi));
}

// ---------------------------------------------------------------------------
// Entry point
// ---------------------------------------------------------------------------
extern "C" void kernel_launch(void* const* d_in, const int* in_sizes, int n_in,
                              void* d_out, int out_size) {
    const float* x    = (const float*)d_in[0];
    const float* Wx   = (const float*)d_in[1];
    const float* Wh   = (const float*)d_in[2];
    const float* bh   = (const float*)d_in[3];
    const float* Wout = (const float*)d_in[4];
    const float* bout = (const float*)d_in[5];
    float* out = (float*)d_out;

    cudaFuncSetAttribute(gemm_rec_tc, cudaFuncAttributeMaxDynamicSharedMemorySize, SMEM_REC);
    cudaFuncSetAttribute(gemm_log_tc, cudaFuncAttributeMaxDynamicSharedMemorySize, SMEM_LOG);

    const int gate_blocks = (BB * HH) / 256;

    gates_kernel<<<gate_blocks, 256>>>(x, Wx, bh, 0, 1);
    for (int t = 1; t < TT; t++) {
        gemm_rec_tc<<<128, THREADS, SMEM_REC>>>(Wh, t);         // 64 N-tiles x 2 M-tiles
        gates_kernel<<<gate_blocks, 256>>>(x, Wx, bh, t, 0);
    }
    gemm_log_tc<<<dim3(500, 1, TT), THREADS, SMEM_LOG>>>(Wout, bout, out);
}

// round 5
// speedup vs baseline: 3.8154x; 1.2520x over previous
#include <cuda_runtime.h>
#include <cuda_bf16.h>
#include <math.h>
#include <stdint.h>

#define BB 256
#define TT 8
#define HH 1024
#define VV 32000
#define G4 4096

#define BK 64            // k elems per chunk (64 bf16 = 128 B row)
#define NCHUNK (HH / BK) // 16
#define THREADS 512      // 16 warps

#define SWZ(off) ((off) ^ (((off) >> 3) & 0x70))

// ---------------------------------------------------------------------------
// scratch (device globals only)
// ---------------------------------------------------------------------------
__device__ __nv_bfloat16 g_hh[TT][BB][HH];
__device__ __nv_bfloat16 g_hl[TT][BB][HH];
__device__ float g_c[BB][HH];
__device__ float g_acc[BB][G4];

// ---------------------------------------------------------------------------
// PTX helpers (sm_80-level only)
// ---------------------------------------------------------------------------
__device__ __forceinline__ uint32_t smem_to_u32(const void* p) {
    uint32_t a;
    asm("{ .reg .u64 t; cvta.to.shared.u64 t, %1; cvt.u32.u64 %0, t; }" : "=r"(a) : "l"(p));
    return a;
}
__device__ __forceinline__ void ldsm4(uint32_t* r, uint32_t addr) {
    asm volatile("ldmatrix.sync.aligned.m8n8.x4.shared.b16 {%0,%1,%2,%3}, [%4];"
                 : "=r"(r[0]), "=r"(r[1]), "=r"(r[2]), "=r"(r[3]) : "r"(addr));
}
__device__ __forceinline__ void mma16816(float* c, const uint32_t* a, const uint32_t* b) {
    asm volatile(
        "mma.sync.aligned.m16n8k16.row.col.f32.bf16.bf16.f32 "
        "{%0,%1,%2,%3}, {%4,%5,%6,%7}, {%8,%9}, {%0,%1,%2,%3};"
        : "+f"(c[0]), "+f"(c[1]), "+f"(c[2]), "+f"(c[3])
        : "r"(a[0]), "r"(a[1]), "r"(a[2]), "r"(a[3]), "r"(b[0]), "r"(b[1]));
}
__device__ __forceinline__ void cp16(uint32_t dst, const void* src) {
    asm volatile("cp.async.cg.shared.global [%0], [%1], 16;" :: "r"(dst), "l"(src));
}
#define CP_COMMIT() asm volatile("cp.async.commit_group;" ::: "memory")
#define CP_WAIT0()  asm volatile("cp.async.wait_group 0;" ::: "memory")

__device__ __forceinline__ uint32_t split2(float x, float y, uint32_t& lo) {
    __nv_bfloat16 hx = __float2bfloat16(x);
    __nv_bfloat16 hy = __float2bfloat16(y);
    __nv_bfloat16 lx = __float2bfloat16(x - __bfloat162float(hx));
    __nv_bfloat16 ly = __float2bfloat16(y - __bfloat162float(hy));
    __nv_bfloat162 ph; ph.x = hx; ph.y = hy;
    __nv_bfloat162 pl; pl.x = lx; pl.y = ly;
    lo = *(uint32_t*)&pl;
    return *(uint32_t*)&ph;
}

// ---------------------------------------------------------------------------
// Decoupled loaders (all 512 threads participate in both A and B)
// Stage layout: [Ah 16K][Al 16K][Bh BN*128][Bl BN*128], BN = 32*NT
// ---------------------------------------------------------------------------
__device__ __forceinline__ void cpasync_A(const __nv_bfloat16* __restrict__ Ahg,
                                          const __nv_bfloat16* __restrict__ Alg,
                                          uint32_t stage_u32, int kc, int tid) {
    #pragma unroll
    for (int u = 0; u < 2; u++) {
        const int idx = tid * 2 + u;        // 0..1023 16B units
        const int row = idx >> 3;           // 0..127
        const int j   = idx & 7;            // 16B column chunk
        const uint32_t off = SWZ((uint32_t)(row * 128 + j * 16));
        cp16(stage_u32 + off,         Ahg + (size_t)row * HH + kc * BK + j * 8);
        cp16(stage_u32 + 16384 + off, Alg + (size_t)row * HH + kc * BK + j * 8);
    }
}

template <int NT>
__device__ __forceinline__ void ldg_B(const float* __restrict__ Bg, int kc, int tid,
                                      float4* Bf) {
    #pragma unroll
    for (int it = 0; it < NT; it++) {
        const int idx = tid + it * THREADS;   // float4 index, 0..BN*16-1
        const int row = idx >> 4;
        const int c4  = idx & 15;
        Bf[it] = *(const float4*)(Bg + (size_t)row * HH + kc * BK + c4 * 4);
    }
}

template <int NT>
__device__ __forceinline__ void sts_B(char* stage, int tid, const float4* Bf) {
    constexpr int BN = 32 * NT;
    constexpr int OFF_BH = 32768;
    constexpr int OFF_BL = 32768 + BN * 128;
    #pragma unroll
    for (int it = 0; it < NT; it++) {
        const int idx = tid + it * THREADS;
        const int row = idx >> 4;
        const int c4  = idx & 15;
        uint2 vh, vl;
        vh.x = split2(Bf[it].x, Bf[it].y, vl.x);
        vh.y = split2(Bf[it].z, Bf[it].w, vl.y);
        const uint32_t off = SWZ((uint32_t)(row * 128 + c4 * 8));
        *(uint2*)(stage + OFF_BH + off) = vh;
        *(uint2*)(stage + OFF_BL + off) = vl;
    }
}

// ---------------------------------------------------------------------------
// GEMM tile: CTA tile 128 x BN, warp tile m32 x (8*NT). 16 warps.
// ---------------------------------------------------------------------------
template <int NT>
__device__ __forceinline__ void gemm_body(const __nv_bfloat16* Ahg,
                                          const __nv_bfloat16* Alg,
                                          const float* Bg, const float* bias,
                                          float* C, int ldc) {
    constexpr int BN = 32 * NT;
    constexpr int OFF_BH = 32768;
    constexpr int OFF_BL = 32768 + BN * 128;
    constexpr int STAGE  = 32768 + 2 * BN * 128;

    extern __shared__ char smem[];
    const uint32_t sbase = smem_to_u32(smem);
    const int tid  = threadIdx.x;
    const int lane = tid & 31;
    const int wid  = tid >> 5;
    const int wm   = wid & 3;          // m32 block
    const int wn   = (wid >> 2) & 3;   // n(8*NT) block

    float acc[2][NT][4];
    #pragma unroll
    for (int mt = 0; mt < 2; mt++)
        #pragma unroll
        for (int nt = 0; nt < NT; nt++)
            #pragma unroll
            for (int i = 0; i < 4; i++) acc[mt][nt][i] = 0.0f;

    const int a_row = (lane & 15);
    const int a_kb  = (lane >> 4) * 16;
    const int b_row = (lane & 7) + ((lane >> 4) << 3);
    const int b_kb  = ((lane >> 3) & 1) * 16;

    float4 Bf[NT];

    // Prologue: chunk 0
    ldg_B<NT>(Bg, 0, tid, Bf);
    cpasync_A(Ahg, Alg, sbase, 0, tid);
    CP_COMMIT();
    sts_B<NT>(smem, tid, Bf);
    CP_WAIT0();
    __syncthreads();

    for (int kc = 0; kc < NCHUNK; kc++) {
        const int st = kc & 1;
        const uint32_t sb = sbase + st * STAGE;
        char* alt = smem + (st ^ 1) * STAGE;

        // Issue next chunk's loads up front (LDG into regs, cp.async for A).
        if (kc + 1 < NCHUNK) {
            ldg_B<NT>(Bg, kc + 1, tid, Bf);
            cpasync_A(Ahg, Alg, sbase + (st ^ 1) * STAGE, kc + 1, tid);
            CP_COMMIT();
        }

        // MMAs on current stage (covers the LDG latency above).
        #pragma unroll
        for (int k16 = 0; k16 < 4; k16++) {
            const int kb = k16 * 32;
            uint32_t ah[2][4], al[2][4];
            #pragma unroll
            for (int mt = 0; mt < 2; mt++) {
                const uint32_t off = SWZ((uint32_t)((wm * 32 + mt * 16 + a_row) * 128 + kb + a_kb));
                ldsm4(ah[mt], sb + off);
                ldsm4(al[mt], sb + 16384 + off);
            }
            uint32_t bh[NT][2], bl[NT][2];
            #pragma unroll
            for (int nq = 0; nq < NT / 2; nq++) {
                const uint32_t off = SWZ((uint32_t)((wn * NT * 8 + nq * 16 + b_row) * 128 + kb + b_kb));
                uint32_t r[4];
                ldsm4(r, sb + OFF_BH + off);
                bh[nq * 2][0] = r[0]; bh[nq * 2][1] = r[1];
                bh[nq * 2 + 1][0] = r[2]; bh[nq * 2 + 1][1] = r[3];
                ldsm4(r, sb + OFF_BL + off);
                bl[nq * 2][0] = r[0]; bl[nq * 2][1] = r[1];
                bl[nq * 2 + 1][0] = r[2]; bl[nq * 2 + 1][1] = r[3];
            }
            #pragma unroll
            for (int mt = 0; mt < 2; mt++)
                #pragma unroll
                for (int nt = 0; nt < NT; nt++) {
                    mma16816(acc[mt][nt], ah[mt], bh[nt]);
                    mma16816(acc[mt][nt], ah[mt], bl[nt]);
                    mma16816(acc[mt][nt], al[mt], bh[nt]);
                }
        }

        // Split + store next chunk's B (data has long since landed).
        if (kc + 1 < NCHUNK) {
            sts_B<NT>(alt, tid, Bf);
            CP_WAIT0();
        }
        __syncthreads();
    }

    const int erow = (lane >> 2);
    const int ecol = (lane & 3) * 2;
    #pragma unroll
    for (int mt = 0; mt < 2; mt++) {
        #pragma unroll
        for (int nt = 0; nt < NT; nt++) {
            const int r0 = wm * 32 + mt * 16 + erow;
            const int cc = wn * NT * 8 + nt * 8 + ecol;
            float b0 = 0.f, b1 = 0.f;
            if (bias) { b0 = bias[cc]; b1 = bias[cc + 1]; }
            float2 v0 = make_float2(acc[mt][nt][0] + b0, acc[mt][nt][1] + b1);
            float2 v1 = make_float2(acc[mt][nt][2] + b0, acc[mt][nt][3] + b1);
            *(float2*)(C + (size_t)r0 * ldc + cc)       = v0;
            *(float2*)(C + (size_t)(r0 + 8) * ldc + cc) = v1;
        }
    }
}

// ---------------------------------------------------------------------------
// Global wrappers
// ---------------------------------------------------------------------------
#define SMEM_REC (2 * (32768 + 2 * 64 * 128))    //  98304 (NT=2, BN=64)
#define SMEM_LOG (2 * (32768 + 2 * 128 * 128))   // 131072 (NT=4, BN=128)

__global__ void __launch_bounds__(THREADS, 1) gemm_rec_tc(const float* __restrict__ Wh, int t) {
    const int mtile = blockIdx.x & 1;
    const int ntile = blockIdx.x >> 1;           // 0..63, BN=64
    gemm_body<2>(&g_hh[t - 1][mtile * 128][0], &g_hl[t - 1][mtile * 128][0],
                 Wh + (size_t)t * G4 * HH + (size_t)ntile * 64 * HH,
                 nullptr,
                 &g_acc[mtile * 128][ntile * 64], G4);
}

__global__ void __launch_bounds__(THREADS, 1) gemm_log_tc(const float* __restrict__ Wout,
                                                          const float* __restrict__ bout,
                                                          float* __restrict__ out) {
    const int t = blockIdx.z;
    const int mtile = blockIdx.x & 1;            // adjacent CTAs share Wout tile via L2
    const int ntile = blockIdx.x >> 1;           // 0..249, BN=128
    gemm_body<4>(&g_hh[t][mtile * 128][0], &g_hl[t][mtile * 128][0],
                 Wout + (size_t)t * VV * HH + (size_t)ntile * 128 * HH,
                 bout + (size_t)t * VV + ntile * 128,
                 out + (size_t)mtile * 128 * TT * VV + (size_t)t * VV + ntile * 128,
                 TT * VV);
}

// ---------------------------------------------------------------------------
// Gates / cell update (emits split-bf16 h)
// ---------------------------------------------------------------------------
__device__ __forceinline__ float sigf(float v) { return 1.0f / (1.0f + expf(-v)); }

__global__ void gates_kernel(const float* __restrict__ x,
                             const float* __restrict__ Wx,
                             const float* __restrict__ bh,
                             int t, int first) {
    const int idx = blockIdx.x * blockDim.x + threadIdx.x;
    const int b = idx >> 10;
    const int hh = idx & (HH - 1);

    const float xb = x[b * TT + t];
    const float* wx  = Wx + (size_t)t * 4 * HH;
    const float* bht = bh + (size_t)t * 4 * HH;
    const float* acc = &g_acc[b][0];

    float p[4];
    #pragma unroll
    for (int g = 0; g < 4; g++) {
        float v = xb * wx[g * HH + hh];
        if (!first) v += acc[g * HH + hh] + bht[g * HH + hh];
        p[g] = v;
    }
    const float f_ = sigf(p[0]);
    const float i_ = sigf(p[1]);
    const float cb = tanhf(p[2]);
    const float o_ = sigf(p[3]);

    float c = first ? (i_ * cb) : fmaf(f_, g_c[b][hh], i_ * cb);
    g_c[b][hh] = c;
    const float hv = o_ * tanhf(c);
    __nv_bfloat16 hhi = __float2bfloat16(hv);
    g_hh[t][b][hh] = hhi;
    g_hl[t][b][hh] = __float2bfloat16(hv - __bfloat162float(hhi));
}

// ---------------------------------------------------------------------------
// Entry point
// ---------------------------------------------------------------------------
extern "C" void kernel_launch(void* const* d_in, const int* in_sizes, int n_in,
                              void* d_out, int out_size) {
    const float* x    = (const float*)d_in[0];
    const float* Wx   = (const float*)d_in[1];
    const float* Wh   = (const float*)d_in[2];
    const float* bh   = (const float*)d_in[3];
    const float* Wout = (const float*)d_in[4];
    const float* bout = (const float*)d_in[5];
    float* out = (float*)d_out;

    cudaFuncSetAttribute(gemm_rec_tc, cudaFuncAttributeMaxDynamicSharedMemorySize, SMEM_REC);
    cudaFuncSetAttribute(gemm_log_tc, cudaFuncAttributeMaxDynamicSharedMemorySize, SMEM_LOG);

    const int gate_blocks = (BB * HH) / 256;

    gates_kernel<<<gate_blocks, 256>>>(x, Wx, bh, 0, 1);
    for (int t = 1; t < TT; t++) {
        gemm_rec_tc<<<128, THREADS, SMEM_REC>>>(Wh, t);         // 64 N-tiles x 2 M-tiles
        gates_kernel<<<gate_blocks, 256>>>(x, Wx, bh, t, 0);
    }
    gemm_log_tc<<<dim3(500, 1, TT), THREADS, SMEM_LOG>>>(Wout, bout, out);
}

// round 6
// speedup vs baseline: 3.8973x; 1.0215x over previous
#include <cuda_runtime.h>
#include <cuda_bf16.h>
#include <math.h>
#include <stdint.h>

#define BB 256
#define TT 8
#define HH 1024
#define VV 32000
#define G4 4096

#define BK 64            // k elems per chunk (64 bf16 = 128 B row)
#define NCHUNK (HH / BK) // 16
#define THREADS 512      // 16 warps, 4m x 4n warp grid

#define SWZ(off) ((off) ^ (((off) >> 3) & 0x70))

// ---------------------------------------------------------------------------
// scratch (device globals only)
// ---------------------------------------------------------------------------
__device__ __nv_bfloat16 g_hh[TT][BB][HH];
__device__ __nv_bfloat16 g_hl[TT][BB][HH];
__device__ float g_c[BB][HH];
__device__ float g_acc[BB][G4];

// ---------------------------------------------------------------------------
// PTX helpers (sm_80-level only)
// ---------------------------------------------------------------------------
__device__ __forceinline__ uint32_t smem_to_u32(const void* p) {
    uint32_t a;
    asm("{ .reg .u64 t; cvta.to.shared.u64 t, %1; cvt.u32.u64 %0, t; }" : "=r"(a) : "l"(p));
    return a;
}
__device__ __forceinline__ void ldsm4(uint32_t* r, uint32_t addr) {
    asm volatile("ldmatrix.sync.aligned.m8n8.x4.shared.b16 {%0,%1,%2,%3}, [%4];"
                 : "=r"(r[0]), "=r"(r[1]), "=r"(r[2]), "=r"(r[3]) : "r"(addr));
}
__device__ __forceinline__ void mma16816(float* c, const uint32_t* a, const uint32_t* b) {
    asm volatile(
        "mma.sync.aligned.m16n8k16.row.col.f32.bf16.bf16.f32 "
        "{%0,%1,%2,%3}, {%4,%5,%6,%7}, {%8,%9}, {%0,%1,%2,%3};"
        : "+f"(c[0]), "+f"(c[1]), "+f"(c[2]), "+f"(c[3])
        : "r"(a[0]), "r"(a[1]), "r"(a[2]), "r"(a[3]), "r"(b[0]), "r"(b[1]));
}
__device__ __forceinline__ void cp16(uint32_t dst, const void* src) {
    asm volatile("cp.async.cg.shared.global [%0], [%1], 16;" :: "r"(dst), "l"(src));
}
#define CP_COMMIT() asm volatile("cp.async.commit_group;" ::: "memory")
#define CP_WAIT0()  asm volatile("cp.async.wait_group 0;" ::: "memory")

__device__ __forceinline__ uint32_t split2(float x, float y, uint32_t& lo) {
    __nv_bfloat16 hx = __float2bfloat16(x);
    __nv_bfloat16 hy = __float2bfloat16(y);
    __nv_bfloat16 lx = __float2bfloat16(x - __bfloat162float(hx));
    __nv_bfloat16 ly = __float2bfloat16(y - __bfloat162float(hy));
    __nv_bfloat162 ph; ph.x = hx; ph.y = hy;
    __nv_bfloat162 pl; pl.x = lx; pl.y = ly;
    lo = *(uint32_t*)&pl;
    return *(uint32_t*)&ph;
}

// ---------------------------------------------------------------------------
// Loaders. Stage layout: [Ah BM*128][Al BM*128][Bh BN*128][Bl BN*128]
// BM = MT*64, BN = NT*32 (warp grid 4x4, warp tile m(MT*16) x n(NT*8)).
// ---------------------------------------------------------------------------
template <int MT>
__device__ __forceinline__ void cpasync_A(const __nv_bfloat16* __restrict__ Ahg,
                                          const __nv_bfloat16* __restrict__ Alg,
                                          uint32_t stage_u32, int kc, int tid) {
    constexpr int BM = MT * 64;
    #pragma unroll
    for (int u = 0; u < MT; u++) {            // BM*8 16B-units per split
        const int idx = tid + u * THREADS;
        const int row = idx >> 3;
        const int j   = idx & 7;
        const uint32_t off = SWZ((uint32_t)(row * 128 + j * 16));
        cp16(stage_u32 + off,            Ahg + (size_t)row * HH + kc * BK + j * 8);
        cp16(stage_u32 + BM * 128 + off, Alg + (size_t)row * HH + kc * BK + j * 8);
    }
}

template <int NT>
__device__ __forceinline__ void ldg_B(const float* __restrict__ Bg, int kc, int tid,
                                      float4* Bf) {
    #pragma unroll
    for (int it = 0; it < NT; it++) {         // BN*16 float4s total
        const int idx = tid + it * THREADS;
        const int row = idx >> 4;
        const int c4  = idx & 15;
        Bf[it] = *(const float4*)(Bg + (size_t)row * HH + kc * BK + c4 * 4);
    }
}

template <int MT, int NT>
__device__ __forceinline__ void sts_B(char* stage, int tid, const float4* Bf) {
    constexpr int BM = MT * 64;
    constexpr int BN = NT * 32;
    constexpr int OFF_BH = 2 * BM * 128;
    constexpr int OFF_BL = OFF_BH + BN * 128;
    #pragma unroll
    for (int it = 0; it < NT; it++) {
        const int idx = tid + it * THREADS;
        const int row = idx >> 4;
        const int c4  = idx & 15;
        uint2 vh, vl;
        vh.x = split2(Bf[it].x, Bf[it].y, vl.x);
        vh.y = split2(Bf[it].z, Bf[it].w, vl.y);
        const uint32_t off = SWZ((uint32_t)(row * 128 + c4 * 8));
        *(uint2*)(stage + OFF_BH + off) = vh;
        *(uint2*)(stage + OFF_BL + off) = vl;
    }
}

// ---------------------------------------------------------------------------
// GEMM tile: CTA tile (MT*64) x (NT*32). 16 warps: wm = wid&3, wn = wid>>2.
// Warp tile: m(MT*16) x n(NT*8).
// ---------------------------------------------------------------------------
template <int MT, int NT>
__device__ __forceinline__ void gemm_body(const __nv_bfloat16* Ahg,
                                          const __nv_bfloat16* Alg,
                                          const float* Bg, const float* bias,
                                          float* C, int ldc) {
    constexpr int BM = MT * 64;
    constexpr int BN = NT * 32;
    constexpr int OFF_AL = BM * 128;
    constexpr int OFF_BH = 2 * BM * 128;
    constexpr int OFF_BL = OFF_BH + BN * 128;
    constexpr int STAGE  = 2 * BM * 128 + 2 * BN * 128;

    extern __shared__ char smem[];
    const uint32_t sbase = smem_to_u32(smem);
    const int tid  = threadIdx.x;
    const int lane = tid & 31;
    const int wid  = tid >> 5;
    const int wm   = wid & 3;
    const int wn   = (wid >> 2) & 3;

    float acc[MT][NT][4];
    #pragma unroll
    for (int mt = 0; mt < MT; mt++)
        #pragma unroll
        for (int nt = 0; nt < NT; nt++)
            #pragma unroll
            for (int i = 0; i < 4; i++) acc[mt][nt][i] = 0.0f;

    const int a_row = (lane & 15);
    const int a_kb  = (lane >> 4) * 16;
    const int b_row = (lane & 7) + ((lane >> 4) << 3);
    const int b_kb  = ((lane >> 3) & 1) * 16;

    float4 Bf[NT];

    ldg_B<NT>(Bg, 0, tid, Bf);
    cpasync_A<MT>(Ahg, Alg, sbase, 0, tid);
    CP_COMMIT();
    sts_B<MT, NT>(smem, tid, Bf);
    CP_WAIT0();
    __syncthreads();

    for (int kc = 0; kc < NCHUNK; kc++) {
        const int st = kc & 1;
        const uint32_t sb = sbase + st * STAGE;
        char* alt = smem + (st ^ 1) * STAGE;

        if (kc + 1 < NCHUNK) {
            ldg_B<NT>(Bg, kc + 1, tid, Bf);
            cpasync_A<MT>(Ahg, Alg, sbase + (st ^ 1) * STAGE, kc + 1, tid);
            CP_COMMIT();
        }

        #pragma unroll
        for (int k16 = 0; k16 < 4; k16++) {
            const int kb = k16 * 32;
            uint32_t ah[MT][4], al[MT][4];
            #pragma unroll
            for (int mt = 0; mt < MT; mt++) {
                const uint32_t off = SWZ((uint32_t)((wm * MT * 16 + mt * 16 + a_row) * 128 + kb + a_kb));
                ldsm4(ah[mt], sb + off);
                ldsm4(al[mt], sb + OFF_AL + off);
            }
            uint32_t bh[NT][2], bl[NT][2];
            #pragma unroll
            for (int nq = 0; nq < NT / 2; nq++) {
                const uint32_t off = SWZ((uint32_t)((wn * NT * 8 + nq * 16 + b_row) * 128 + kb + b_kb));
                uint32_t r[4];
                ldsm4(r, sb + OFF_BH + off);
                bh[nq * 2][0] = r[0]; bh[nq * 2][1] = r[1];
                bh[nq * 2 + 1][0] = r[2]; bh[nq * 2 + 1][1] = r[3];
                ldsm4(r, sb + OFF_BL + off);
                bl[nq * 2][0] = r[0]; bl[nq * 2][1] = r[1];
                bl[nq * 2 + 1][0] = r[2]; bl[nq * 2 + 1][1] = r[3];
            }
            // Pass-outermost: consecutive MMAs hit different accumulators.
            #pragma unroll
            for (int mt = 0; mt < MT; mt++)
                #pragma unroll
                for (int nt = 0; nt < NT; nt++)
                    mma16816(acc[mt][nt], ah[mt], bh[nt]);
            #pragma unroll
            for (int mt = 0; mt < MT; mt++)
                #pragma unroll
                for (int nt = 0; nt < NT; nt++)
                    mma16816(acc[mt][nt], ah[mt], bl[nt]);
            #pragma unroll
            for (int mt = 0; mt < MT; mt++)
                #pragma unroll
                for (int nt = 0; nt < NT; nt++)
                    mma16816(acc[mt][nt], al[mt], bh[nt]);
        }

        if (kc + 1 < NCHUNK) {
            sts_B<MT, NT>(alt, tid, Bf);
            CP_WAIT0();
        }
        __syncthreads();
    }

    const int erow = (lane >> 2);
    const int ecol = (lane & 3) * 2;
    #pragma unroll
    for (int mt = 0; mt < MT; mt++) {
        #pragma unroll
        for (int nt = 0; nt < NT; nt++) {
            const int r0 = wm * MT * 16 + mt * 16 + erow;
            const int cc = wn * NT * 8 + nt * 8 + ecol;
            float b0 = 0.f, b1 = 0.f;
            if (bias) { b0 = bias[cc]; b1 = bias[cc + 1]; }
            float2 v0 = make_float2(acc[mt][nt][0] + b0, acc[mt][nt][1] + b1);
            float2 v1 = make_float2(acc[mt][nt][2] + b0, acc[mt][nt][3] + b1);
            *(float2*)(C + (size_t)r0 * ldc + cc)       = v0;
            *(float2*)(C + (size_t)(r0 + 8) * ldc + cc) = v1;
        }
    }
}

// ---------------------------------------------------------------------------
// Global wrappers
// ---------------------------------------------------------------------------
#define SMEM_REC (2 * (2 * 128 * 128 + 2 * 64 * 128))   //  98304 (MT=2, NT=2)
#define SMEM_LOG (2 * (2 * 256 * 128 + 2 * 64 * 128))   // 163840 (MT=4, NT=2)

__global__ void __launch_bounds__(THREADS, 1) gemm_rec_tc(const float* __restrict__ Wh, int t) {
    const int mtile = blockIdx.x & 1;
    const int ntile = blockIdx.x >> 1;           // 0..63, BN=64
    gemm_body<2, 2>(&g_hh[t - 1][mtile * 128][0], &g_hl[t - 1][mtile * 128][0],
                    Wh + (size_t)t * G4 * HH + (size_t)ntile * 64 * HH,
                    nullptr,
                    &g_acc[mtile * 128][ntile * 64], G4);
}

__global__ void __launch_bounds__(THREADS, 1) gemm_log_tc(const float* __restrict__ Wout,
                                                          const float* __restrict__ bout,
                                                          float* __restrict__ out) {
    const int t = blockIdx.z;
    const int ntile = blockIdx.x;                // 0..499, BN=64, BM=256 (all batch)
    gemm_body<4, 2>(&g_hh[t][0][0], &g_hl[t][0][0],
                    Wout + (size_t)t * VV * HH + (size_t)ntile * 64 * HH,
                    bout + (size_t)t * VV + ntile * 64,
                    out + (size_t)t * VV + ntile * 64,
                    TT * VV);
}

// ---------------------------------------------------------------------------
// Gates / cell update (emits split-bf16 h)
// ---------------------------------------------------------------------------
__device__ __forceinline__ float sigf(float v) { return 1.0f / (1.0f + expf(-v)); }

__global__ void gates_kernel(const float* __restrict__ x,
                             const float* __restrict__ Wx,
                             const float* __restrict__ bh,
                             int t, int first) {
    const int idx = blockIdx.x * blockDim.x + threadIdx.x;
    const int b = idx >> 10;
    const int hh = idx & (HH - 1);

    const float xb = x[b * TT + t];
    const float* wx  = Wx + (size_t)t * 4 * HH;
    const float* bht = bh + (size_t)t * 4 * HH;
    const float* acc = &g_acc[b][0];

    float p[4];
    #pragma unroll
    for (int g = 0; g < 4; g++) {
        float v = xb * wx[g * HH + hh];
        if (!first) v += acc[g * HH + hh] + bht[g * HH + hh];
        p[g] = v;
    }
    const float f_ = sigf(p[0]);
    const float i_ = sigf(p[1]);
    const float cb = tanhf(p[2]);
    const float o_ = sigf(p[3]);

    float c = first ? (i_ * cb) : fmaf(f_, g_c[b][hh], i_ * cb);
    g_c[b][hh] = c;
    const float hv = o_ * tanhf(c);
    __nv_bfloat16 hhi = __float2bfloat16(hv);
    g_hh[t][b][hh] = hhi;
    g_hl[t][b][hh] = __float2bfloat16(hv - __bfloat162float(hhi));
}

// ---------------------------------------------------------------------------
// Entry point
// ---------------------------------------------------------------------------
extern "C" void kernel_launch(void* const* d_in, const int* in_sizes, int n_in,
                              void* d_out, int out_size) {
    const float* x    = (const float*)d_in[0];
    const float* Wx   = (const float*)d_in[1];
    const float* Wh   = (const float*)d_in[2];
    const float* bh   = (const float*)d_in[3];
    const float* Wout = (const float*)d_in[4];
    const float* bout = (const float*)d_in[5];
    float* out = (float*)d_out;

    cudaFuncSetAttribute(gemm_rec_tc, cudaFuncAttributeMaxDynamicSharedMemorySize, SMEM_REC);
    cudaFuncSetAttribute(gemm_log_tc, cudaFuncAttributeMaxDynamicSharedMemorySize, SMEM_LOG);

    const int gate_blocks = (BB * HH) / 256;

    gates_kernel<<<gate_blocks, 256>>>(x, Wx, bh, 0, 1);
    for (int t = 1; t < TT; t++) {
        gemm_rec_tc<<<128, THREADS, SMEM_REC>>>(Wh, t);
        gates_kernel<<<gate_blocks, 256>>>(x, Wx, bh, t, 0);
    }
    gemm_log_tc<<<dim3(500, 1, TT), THREADS, SMEM_LOG>>>(Wout, bout, out);
}